// round 11
// baseline (speedup 1.0000x reference)
#include <cuda_runtime.h>
#include <math.h>

// ---------------- problem constants (fixed shapes) ----------------
#define Bb   112      // N*W = 2*56
#define NP   224      // NHH*Hh
#define PADN 19
#define EPSN 5e-5f
#define EPS2 (5e-5f * 5e-5f)
#define MFIX 1.5f     // fixed logsumexp shift; |ss| <= sqrt(2) provably

// ---------------- scratch (device globals; no allocs) --------------
__device__ float g_qkv[Bb * 5376];    // (b, o*56+h) flat == (b, t*96+f) view
__device__ int   g_undo[Bb * NP];
__device__ int   g_srcr[Bb * NP];
__device__ float g_wb [Bb * 9600];    // (b, u*2400 + t*32 + f)
__device__ float g_vb [Bb * 19200];   // (b, u*4800 + t*64 + f)
__device__ float g_ret[Bb * 38400];   // (b, g*4800 + u*1200 + k*400 + i*16 + e)
__device__ float g_bs [Bb * 2400];    // (b, g*300 + u*75 + k*25 + i)
__device__ float g_pn [Bb * 4 * 300]; // partial sum-of-squares per 32-channel slab

// ---------------- packed f32x2 helpers (B300 dual-issue fp32) ----------------
__device__ __forceinline__ unsigned long long pack2(float lo, float hi) {
    unsigned long long r;
    asm("mov.b64 %0, {%1, %2};" : "=l"(r) : "r"(__float_as_uint(lo)), "r"(__float_as_uint(hi)));
    return r;
}
__device__ __forceinline__ void fma2(unsigned long long& d, unsigned long long a, unsigned long long b) {
    asm("fma.rn.f32x2 %0, %1, %2, %0;" : "+l"(d) : "l"(a), "l"(b));
}
__device__ __forceinline__ void unpack2(unsigned long long v, float& lo, float& hi) {
    unsigned int a, b;
    asm("mov.b64 {%0, %1}, %2;" : "=r"(a), "=r"(b) : "l"(v));
    lo = __uint_as_float(a); hi = __uint_as_float(b);
}

// ---------------- K1: qkv = conv_w @ x, + BN ----------------
__global__ void k1_qkv(const float* __restrict__ x, const float* __restrict__ cw,
                       const float* __restrict__ gamma, const float* __restrict__ beta) {
    __shared__ float xs[64 * 56];
    __shared__ float ws[48 * 64];
    int n = blockIdx.x / 56, h = blockIdx.x % 56;
    int o0 = blockIdx.y * 48;
    for (int idx = threadIdx.x; idx < 64 * 56; idx += blockDim.x) {
        int c = idx / 56, w = idx % 56;
        xs[idx] = x[((n * 64 + c) * 56 + h) * 56 + w];
    }
    for (int idx = threadIdx.x; idx < 48 * 64; idx += blockDim.x)
        ws[idx] = cw[o0 * 64 + idx];
    __syncthreads();
    const float invbn = rsqrtf(1.0f + 1e-5f);
    for (int idx = threadIdx.x; idx < 48 * 56; idx += blockDim.x) {
        int oo = idx / 56, w = idx % 56;
        int o = o0 + oo;
        float s = 0.f;
        #pragma unroll 16
        for (int c = 0; c < 64; c++) s += ws[oo * 64 + c] * xs[c * 56 + w];
        s = s * invbn * gamma[o] + beta[o];
        g_qkv[(n * 56 + w) * 5376 + o * 56 + h] = s;
    }
}

// ---------------- K2: LSH codes + stable argsort (tables only) ----------------
__global__ void k2_sort(const float* __restrict__ rot) {
    __shared__ int code[NP];
    int b = blockIdx.x;
    int tid = threadIdx.x;
    if (tid < NP) {
        int u = tid / 56, t = tid % 56;
        const float* q = &g_qkv[b * 5376 + t * 96];
        float s = 0.f;
        #pragma unroll 8
        for (int f = 0; f < 32; f++) s += q[f] * rot[f * 4 + u];
        code[tid] = (s < 0.f ? 1 : 0) + u * 2;   // argmax([r,-r]) + u*hash_buckets
    }
    __syncthreads();
    if (tid < NP) {
        int c = code[tid];
        int r = 0;
        for (int j = 0; j < NP; j++) {
            int cj = code[j];
            r += (cj < c) || (cj == c && j < tid);   // stable rank
        }
        g_undo[b * NP + tid] = r;
        g_srcr[b * NP + r] = tid % 56;                // mod = indices % H
    }
}

// ---------------- K2b: gather/pad into g_wb/g_vb (grid 112 x 4) ----------------
__global__ __launch_bounds__(256)
void k2b_gather() {
    __shared__ int srcr[56];
    int b = blockIdx.x, u = blockIdx.y;
    int tid = threadIdx.x;
    if (tid < 56) srcr[tid] = g_srcr[b * NP + u * 56 + tid];
    __syncthreads();
    const float* qb = &g_qkv[b * 5376];
    float* wb = &g_wb[b * 9600 + u * 2400];
    float* vb = &g_vb[b * 19200 + u * 4800];
    for (int idx = tid; idx < 2400; idx += 256) {
        int t = idx >> 5, f = idx & 31;
        int tt = (t < 56) ? t : t - PADN;
        wb[idx] = qb[srcr[tt] * 96 + f];
    }
    for (int idx = tid; idx < 4800; idx += 256) {
        int t = idx >> 6, f = idx & 63;
        int tt = (t < 56) ? t : t - PADN;
        vb[idx] = qb[srcr[tt] * 96 + 32 + f];
    }
}

// adjacency roll mapping: j in [0,75) at chunk k -> source t in [0,75)
__device__ __forceinline__ int src_t(int j, int k) {
    if (j < 25) return k * 25 + j;
    if (j < 50) return ((k + 2) % 3) * 25 + (j - 25);
    return ((k + 1) % 3) * 25 + (j - 50);
}

// ---------------- K3: fused scores / cross-group l2norm / softmax / V ----------------
#define K3T 768
__global__ __launch_bounds__(K3T, 2)
void k3_attn(const float* __restrict__ relative) {
    extern __shared__ float smf[];
    float* wr   = smf;            // 2400: raw w_b rows   [g][t][4]
    float* wn   = wr + 2400;      // 2400: l2norm'd rows  [g][t][4]
    float* va   = wn + 2400;      // 4800: v_b rows       [g][t][8]
    float* we   = va + 4800;      // 300:  0.1*w_emb      [t][4]
    float* ve   = we + 300;       // 600:  v_emb padded   [t][8]
    float* ss   = ve + 600;       // 15000: EXP'd scores  [g][i][t] (t-permuted)
    int*   stj  = (int*)(ss + 15000); // 75: roll table j->t

    int blk = blockIdx.x;
    int b = blk / 12, r = blk % 12, u = r / 3, k = r % 3;
    int tid = threadIdx.x;
    int w = tid >> 5, l = tid & 31;

    const float* wbp = &g_wb[b * 9600 + u * 300];
    for (int idx = tid; idx < 2400; idx += K3T)
        wr[idx] = wbp[(idx / 300) * 1200 + (idx % 300)];
    const float* vbp = &g_vb[b * 19200 + u * 600];
    for (int idx = tid; idx < 4800; idx += K3T)
        va[idx] = vbp[(idx / 600) * 2400 + (idx % 600)];
    if (tid < 75) {
        int t = tid;
        int sr = (t < 56) ? t : t - PADN;
        #pragma unroll
        for (int e = 0; e < 4; e++) we[t * 4 + e] = 0.1f * relative[sr * 12 + e];  // F_GW folded
        #pragma unroll
        for (int e = 0; e < 8; e++) ve[t * 8 + e] = relative[sr * 12 + 4 + e];
        stj[t] = src_t(t, k);
    }
    __syncthreads();
    for (int rw = tid; rw < 600; rw += K3T) {
        float4 p = *(const float4*)&wr[rw * 4];
        float s = p.x*p.x + p.y*p.y + p.z*p.z + p.w*p.w;
        float inv = rsqrtf(fmaxf(s, EPS2));
        float4 q; q.x = p.x*inv; q.y = p.y*inv; q.z = p.z*inv; q.w = p.w*inv;
        *(float4*)&wn[rw * 4] = q;
    }
    __syncthreads();

    // phase 1: warp = j-stripe (stride 24), lane = i. wn/wej warp-broadcast;
    // a re-loaded from smem per (j,g) to stay under the 42-reg cap.
    if (l < 25) {
        int ti = k * 25 + l;
        for (int j = w; j < 75; j += 24) {
            int tj = stj[j];
            float4 wej = *(const float4*)&we[tj * 4];
            float sv[8];
            float sq = 0.f;
            #pragma unroll
            for (int g = 0; g < 8; g++) {
                float4 a = *(const float4*)&wr[(g * 75 + ti) * 4];
                float4 m = *(const float4*)&wn[(g * 75 + tj) * 4];
                float rv = a.x*m.x + a.y*m.y + a.z*m.z + a.w*m.w;
                float ev = a.x*wej.x + a.y*wej.y + a.z*wej.z + a.w*wej.w;
                sv[g] = rv + ev;
                sq += rv * rv + ev * ev;
            }
            float inv = rsqrtf(fmaxf(sq, EPS2));
            #pragma unroll
            for (int g = 0; g < 8; g++)
                ss[g * 1875 + l * 75 + tj] = __expf(sv[g] * inv - MFIX);
        }
    }
    __syncthreads();

    // phase 2: 24 warp-roles = (g, sub); sub0: va ch0-3, sub1: va ch4-7, sub2: ve ch0-7.
    // lane = i; vp[t] reads warp-broadcast; row reads stride-75 conflict-free.
    if (l < 25) {
        int g = w / 3, sub = w - g * 3;
        const float* row = &ss[g * 1875 + l * 75];
        float* op = &g_ret[b * 38400 + g * 4800 + u * 1200 + k * 400 + l * 16];
        if (sub < 2) {
            const ulonglong2* vp = (const ulonglong2*)&va[g * 600];
            unsigned long long a0 = 0ull, a1 = 0ull;
            float sum = 0.f;
            for (int t = 0; t < 75; t++) {
                float e0 = row[t];
                sum += e0;
                unsigned long long pe = pack2(e0, e0);
                ulonglong2 v = vp[t * 2 + sub];
                fma2(a0, pe, v.x); fma2(a1, pe, v.y);
            }
            float scale = 1.0f / sum;             // F_GV2 = 1.0
            float lo, hi;
            unpack2(a0, lo, hi);
            op[sub * 4 + 0] = lo * scale; op[sub * 4 + 1] = hi * scale;
            unpack2(a1, lo, hi);
            op[sub * 4 + 2] = lo * scale; op[sub * 4 + 3] = hi * scale;
            if (sub == 0)
                g_bs[b * 2400 + g * 300 + u * 75 + k * 25 + l] = MFIX + __logf(sum);
        } else {
            const ulonglong2* vp = (const ulonglong2*)ve;
            unsigned long long a0 = 0ull, a1 = 0ull, a2 = 0ull, a3 = 0ull;
            float sum = 0.f;
            for (int t = 0; t < 75; t++) {
                float e0 = row[t];
                sum += e0;
                unsigned long long pe = pack2(e0, e0);
                ulonglong2 vA = vp[t * 2];
                ulonglong2 vB = vp[t * 2 + 1];
                fma2(a0, pe, vA.x); fma2(a1, pe, vA.y);
                fma2(a2, pe, vB.x); fma2(a3, pe, vB.y);
            }
            float scale = 0.1f / sum;             // F_GV1 = 0.1
            float lo, hi;
            unpack2(a0, lo, hi); op[8]  = lo * scale; op[9]  = hi * scale;
            unpack2(a1, lo, hi); op[10] = lo * scale; op[11] = hi * scale;
            unpack2(a2, lo, hi); op[12] = lo * scale; op[13] = hi * scale;
            unpack2(a3, lo, hi); op[14] = lo * scale; op[15] = hi * scale;
        }
    }
}

// ---------------- K4a: partial 32-channel sum-of-squares (coalesced) ----------------
__global__ __launch_bounds__(320)
void k4a_partial() {
    int b = blockIdx.x, q = blockIdx.y;
    int t = threadIdx.x;
    if (t >= 300) return;
    const float* p = &g_ret[b * 38400 + q * 32 * 300];
    float s = 0.f;
    #pragma unroll
    for (int c = 0; c < 32; c++) { float v = p[c * 300 + t]; s += v * v; }
    g_pn[(b * 4 + q) * 300 + t] = s;
}

// ---------------- K5: norms + bs-norm + unsort + hash softmax + output ----------------
__global__ __launch_bounds__(512)
void k5_out(float* __restrict__ out) {
    __shared__ float inrm[300];   // INVERSE channel norms
    __shared__ float bsn[300];
    __shared__ int   undo_s[NP];
    __shared__ float prob[NP];
    __shared__ int   off_s[NP];
    __shared__ int   mb_s[NP];
    int b = blockIdx.x;
    int n = b / 56, w = b % 56;
    int tid = threadIdx.x;

    for (int m = tid; m < 300; m += 512) {
        const float* pp = &g_pn[b * 1200 + m];
        float s = pp[0] + pp[300] + pp[600] + pp[900];
        inrm[m] = rsqrtf(fmaxf(s, EPS2));
    }
    for (int m = tid; m < 300; m += 512) {
        const float* p = &g_bs[b * 2400 + m];
        float vals[8], s = 0.f;
        #pragma unroll
        for (int g = 0; g < 8; g++) { vals[g] = p[g * 300]; s += vals[g] * vals[g]; }
        float inv = rsqrtf(fmaxf(s, EPS2));
        float t = 0.f;
        #pragma unroll
        for (int g = 0; g < 8; g++) t += vals[g] * inv;
        bsn[m] = t;
    }
    for (int j = tid; j < NP; j += 512) undo_s[j] = g_undo[b * NP + j];
    __syncthreads();

    if (tid < 56) {
        int h = tid;
        float bv[4];
        float mx = -1e30f;
        #pragma unroll
        for (int u = 0; u < 4; u++) {
            int q = undo_s[u * 56 + h];
            int qu = q / 56, qj = q % 56;
            int kk = qj / 25, i = qj % 25;
            bv[u] = bsn[qu * 75 + qj];
            off_s[u * 56 + h] = qu * 9600 + kk * 3200 + i * 128;
            int mb = kk * 200 + i * 128; mb %= 300;
            mb_s[u * 56 + h] = mb;
            mx = fmaxf(mx, bv[u]);
        }
        float sm = 0.f;
        #pragma unroll
        for (int u = 0; u < 4; u++) { bv[u] = __expf(bv[u] - mx); sm += bv[u]; }
        #pragma unroll
        for (int u = 0; u < 4; u++) prob[u * 56 + h] = bv[u] / sm;
    }
    __syncthreads();

    const float* rp = &g_ret[b * 38400];
    for (int idx = tid; idx < 56 * 64; idx += 512) {
        int h = idx / 64, o = idx % 64;
        float acc = 0.f;
        #pragma unroll
        for (int u = 0; u < 4; u++) {
            int e = u * 56 + h;
            int L0 = off_s[e] + o * 2;
            int m0 = mb_s[e] + o * 2; if (m0 >= 300) m0 -= 300;
            int m1 = m0 + 1;          if (m1 >= 300) m1 = 0;
            float x0 = rp[L0];
            float x1 = rp[L0 + 1];
            acc += prob[e] * (x0 * inrm[m0] + x1 * inrm[m1]);
        }
        out[((n * 64 + o) * 56 + h) * 56 + w] = acc;
    }
}

// ---------------- launch ----------------
extern "C" void kernel_launch(void* const* d_in, const int* in_sizes, int n_in,
                              void* d_out, int out_size) {
    const float* x        = (const float*)d_in[0];
    const float* cw       = (const float*)d_in[1];
    const float* gamma    = (const float*)d_in[2];
    const float* beta     = (const float*)d_in[3];
    const float* relative = (const float*)d_in[4];
    const float* rotations= (const float*)d_in[5];
    float* out = (float*)d_out;

    cudaFuncSetAttribute(k3_attn, cudaFuncAttributeMaxDynamicSharedMemorySize, 102304);

    dim3 g1(112, 2);
    k1_qkv <<<g1, 256>>>(x, cw, gamma, beta);
    k2_sort<<<112, 256>>>(rotations);
    dim3 g2b(112, 4);
    k2b_gather<<<g2b, 256>>>();
    k3_attn<<<Bb * 12, K3T, 102304>>>(relative);
    dim3 g4(112, 4);
    k4a_partial<<<g4, 320>>>();
    k5_out <<<112, 512>>>(out);
}

// round 12
// speedup vs baseline: 1.0168x; 1.0168x over previous
#include <cuda_runtime.h>
#include <math.h>

// ---------------- problem constants (fixed shapes) ----------------
#define Bb   112      // N*W = 2*56
#define NP   224      // NHH*Hh
#define PADN 19
#define EPSN 5e-5f
#define EPS2 (5e-5f * 5e-5f)
#define MFIX 1.5f     // fixed logsumexp shift; |ss| <= sqrt(2) provably

// ---------------- scratch (device globals; no allocs) --------------
__device__ float g_qkv[Bb * 5376];    // (b, o*56+h) flat == (b, t*96+f) view
__device__ int   g_undo[Bb * NP];
__device__ int   g_srcr[Bb * NP];
__device__ float g_wt [Bb * 4 * 2700]; // transposed w tiles: (b,u)[t][c][g], t-stride 36
__device__ float g_vb [Bb * 19200];   // (b, u*4800 + t*64 + f)
__device__ float g_ret[Bb * 38400];   // (b, g*4800 + u*1200 + k*400 + i*16 + e)
__device__ float g_bs [Bb * 2400];    // (b, g*300 + u*75 + k*25 + i)
__device__ float g_pn [Bb * 4 * 300]; // partial sum-of-squares per 32-channel slab

// ---------------- packed f32x2 helpers (B300 dual-issue fp32) ----------------
__device__ __forceinline__ unsigned long long pack2(float lo, float hi) {
    unsigned long long r;
    asm("mov.b64 %0, {%1, %2};" : "=l"(r) : "r"(__float_as_uint(lo)), "r"(__float_as_uint(hi)));
    return r;
}
__device__ __forceinline__ void fma2(unsigned long long& d, unsigned long long a, unsigned long long b) {
    asm("fma.rn.f32x2 %0, %1, %2, %0;" : "+l"(d) : "l"(a), "l"(b));
}
__device__ __forceinline__ unsigned long long add2(unsigned long long a, unsigned long long b) {
    unsigned long long r;
    asm("add.rn.f32x2 %0, %1, %2;" : "=l"(r) : "l"(a), "l"(b));
    return r;
}
__device__ __forceinline__ void unpack2(unsigned long long v, float& lo, float& hi) {
    unsigned int a, b;
    asm("mov.b64 {%0, %1}, %2;" : "=r"(a), "=r"(b) : "l"(v));
    lo = __uint_as_float(a); hi = __uint_as_float(b);
}

// ---------------- K1: qkv = conv_w @ x, + BN ----------------
__global__ void k1_qkv(const float* __restrict__ x, const float* __restrict__ cw,
                       const float* __restrict__ gamma, const float* __restrict__ beta) {
    __shared__ float xs[64 * 56];
    __shared__ float ws[48 * 64];
    int n = blockIdx.x / 56, h = blockIdx.x % 56;
    int o0 = blockIdx.y * 48;
    for (int idx = threadIdx.x; idx < 64 * 56; idx += blockDim.x) {
        int c = idx / 56, w = idx % 56;
        xs[idx] = x[((n * 64 + c) * 56 + h) * 56 + w];
    }
    for (int idx = threadIdx.x; idx < 48 * 64; idx += blockDim.x)
        ws[idx] = cw[o0 * 64 + idx];
    __syncthreads();
    const float invbn = rsqrtf(1.0f + 1e-5f);
    for (int idx = threadIdx.x; idx < 48 * 56; idx += blockDim.x) {
        int oo = idx / 56, w = idx % 56;
        int o = o0 + oo;
        float s = 0.f;
        #pragma unroll 16
        for (int c = 0; c < 64; c++) s += ws[oo * 64 + c] * xs[c * 56 + w];
        s = s * invbn * gamma[o] + beta[o];
        g_qkv[(n * 56 + w) * 5376 + o * 56 + h] = s;
    }
}

// ---------------- K2: LSH codes + stable argsort (tables only) ----------------
__global__ void k2_sort(const float* __restrict__ rot) {
    __shared__ int code[NP];
    int b = blockIdx.x;
    int tid = threadIdx.x;
    if (tid < NP) {
        int u = tid / 56, t = tid % 56;
        const float* q = &g_qkv[b * 5376 + t * 96];
        float s = 0.f;
        #pragma unroll 8
        for (int f = 0; f < 32; f++) s += q[f] * rot[f * 4 + u];
        code[tid] = (s < 0.f ? 1 : 0) + u * 2;   // argmax([r,-r]) + u*hash_buckets
    }
    __syncthreads();
    if (tid < NP) {
        int c = code[tid];
        int r = 0;
        for (int j = 0; j < NP; j++) {
            int cj = code[j];
            r += (cj < c) || (cj == c && j < tid);   // stable rank
        }
        g_undo[b * NP + tid] = r;
        g_srcr[b * NP + r] = tid % 56;                // mod = indices % H
    }
}

// ---------------- K2b: gather/pad into g_wt (transposed) + g_vb ----------------
__global__ __launch_bounds__(256)
void k2b_gather() {
    __shared__ int srcr[NP];
    int b = blockIdx.x, u = blockIdx.y;
    int tid = threadIdx.x;
    if (tid < NP) srcr[tid] = g_srcr[b * NP + tid];
    __syncthreads();
    const float* qb = &g_qkv[b * 5376];
    // w tile transposed: wt[t*36 + c*8 + g] = flat-group-view(F = g*1200 + u*300 + t*4 + c)
    float* wt = &g_wt[(b * 4 + u) * 2700];
    for (int idx = tid; idx < 2400; idx += 256) {
        int t = idx >> 5, rem = idx & 31, c = rem >> 3, g = rem & 7;
        int F = g * 1200 + u * 300 + t * 4 + c;
        int u2 = F / 2400, r2 = F % 2400;
        int t2 = r2 >> 5, f = r2 & 31;
        int tt = (t2 < 56) ? t2 : t2 - PADN;
        wt[t * 36 + c * 8 + g] = qb[srcr[u2 * 56 + tt] * 96 + f];
    }
    float* vb = &g_vb[b * 19200 + u * 4800];
    const int* sru = &srcr[u * 56];
    for (int idx = tid; idx < 4800; idx += 256) {
        int t = idx >> 6, f = idx & 63;
        int tt = (t < 56) ? t : t - PADN;
        vb[idx] = qb[sru[tt] * 96 + 32 + f];
    }
}

// adjacency roll mapping: j in [0,75) at chunk k -> source t in [0,75)
__device__ __forceinline__ int src_t(int j, int k) {
    if (j < 25) return k * 25 + j;
    if (j < 50) return ((k + 2) % 3) * 25 + (j - 25);
    return ((k + 1) % 3) * 25 + (j - 50);
}

// ---------------- K3: fused scores / cross-group l2norm / softmax / V ----------------
// smem floats: wr3 0..2700, wn3 2700..5400, va 5400..10200, we 10200..10500,
//              ve 10500..11100, ss 11100..26100, stj 26100..26175  => 104700 B
#define K3T 512
__global__ __launch_bounds__(K3T, 2)
void k3_attn(const float* __restrict__ relative) {
    extern __shared__ float smf[];
    float* wr3  = smf;                // [t][c][g], stride 36 per t
    float* wn3  = wr3 + 2700;         // l2norm'd, same layout
    float* va   = wn3 + 2700;         // 4800: v_b rows [g][t][8]
    float* we   = va + 4800;          // 300:  0.1*w_emb [t][4]
    float* ve   = we + 300;           // 600:  v_emb padded [t][8]
    float* ss   = ve + 600;           // 15000: EXP'd scores [g][i][t] (t-permuted)
    int*   stj  = (int*)(ss + 15000); // 75: roll table j->t

    int blk = blockIdx.x;
    int b = blk / 12, r = blk % 12, u = r / 3, k = r % 3;
    int tid = threadIdx.x;
    int w = tid >> 5, l = tid & 31;

    const float* wtp = &g_wt[(b * 4 + u) * 2700];
    for (int idx = tid; idx < 2700; idx += K3T) wr3[idx] = wtp[idx];
    const float* vbp = &g_vb[b * 19200 + u * 600];
    for (int idx = tid; idx < 4800; idx += K3T)
        va[idx] = vbp[(idx / 600) * 2400 + (idx % 600)];
    if (tid < 75) {
        int t = tid;
        int sr = (t < 56) ? t : t - PADN;
        #pragma unroll
        for (int e = 0; e < 4; e++) we[t * 4 + e] = 0.1f * relative[sr * 12 + e];  // F_GW folded
        #pragma unroll
        for (int e = 0; e < 8; e++) ve[t * 8 + e] = relative[sr * 12 + 4 + e];
        stj[t] = src_t(t, k);
    }
    __syncthreads();
    // row l2norms: row = (g,t), 4 channels at stride 8 in [t][c][g]
    for (int idx = tid; idx < 600; idx += K3T) {
        int t = idx >> 3, g = idx & 7;
        float v0 = wr3[t * 36 + g];
        float v1 = wr3[t * 36 + 8 + g];
        float v2 = wr3[t * 36 + 16 + g];
        float v3 = wr3[t * 36 + 24 + g];
        float inv = rsqrtf(fmaxf(v0*v0 + v1*v1 + v2*v2 + v3*v3, EPS2));
        wn3[t * 36 + g]      = v0 * inv;
        wn3[t * 36 + 8 + g]  = v1 * inv;
        wn3[t * 36 + 16 + g] = v2 * inv;
        wn3[t * 36 + 24 + g] = v3 * inv;
    }
    __syncthreads();

    // phase 1: lane = i, warp strides j. a hoisted as 8 ulonglong2 (g-packed);
    // m loads warp-broadcast ulonglong2; all math in f32x2 over g-pairs.
    if (l < 25) {
        int ti = k * 25 + l;
        ulonglong2 a2[8];
        {
            const ulonglong2* rp2 = (const ulonglong2*)(wr3 + ti * 36);
            #pragma unroll
            for (int q = 0; q < 8; q++) a2[q] = rp2[q];
        }
        for (int j = w; j < 75; j += 16) {
            int tj = stj[j];
            const ulonglong2* mp2 = (const ulonglong2*)(wn3 + tj * 36);
            float4 wej = *(const float4*)&we[tj * 4];
            unsigned long long wejp[4];
            wejp[0] = pack2(wej.x, wej.x); wejp[1] = pack2(wej.y, wej.y);
            wejp[2] = pack2(wej.z, wej.z); wejp[3] = pack2(wej.w, wej.w);
            unsigned long long rvp[4] = {0ull,0ull,0ull,0ull};
            unsigned long long evp[4] = {0ull,0ull,0ull,0ull};
            #pragma unroll
            for (int c = 0; c < 4; c++) {
                ulonglong2 m01 = mp2[c * 2];
                ulonglong2 m23 = mp2[c * 2 + 1];
                unsigned long long A0 = a2[c * 2].x, A1 = a2[c * 2].y;
                unsigned long long A2 = a2[c * 2 + 1].x, A3 = a2[c * 2 + 1].y;
                fma2(rvp[0], A0, m01.x); fma2(rvp[1], A1, m01.y);
                fma2(rvp[2], A2, m23.x); fma2(rvp[3], A3, m23.y);
                fma2(evp[0], A0, wejp[c]); fma2(evp[1], A1, wejp[c]);
                fma2(evp[2], A2, wejp[c]); fma2(evp[3], A3, wejp[c]);
            }
            unsigned long long sqp = 0ull;
            #pragma unroll
            for (int gp = 0; gp < 4; gp++) { fma2(sqp, rvp[gp], rvp[gp]); fma2(sqp, evp[gp], evp[gp]); }
            float sqlo, sqhi;
            unpack2(sqp, sqlo, sqhi);
            float inv = rsqrtf(fmaxf(sqlo + sqhi, EPS2));
            #pragma unroll
            for (int gp = 0; gp < 4; gp++) {
                float s0, s1;
                unpack2(add2(rvp[gp], evp[gp]), s0, s1);
                ss[(2 * gp) * 1875 + l * 75 + tj]     = __expf(s0 * inv - MFIX);
                ss[(2 * gp + 1) * 1875 + l * 75 + tj] = __expf(s1 * inv - MFIX);
            }
        }
    }
    __syncthreads();

    // phase 2: warp = (g, va-or-ve half); lane = i. vp[t] warp-broadcast;
    // row reads stride-75 conflict-free. No shuffles; pure LDS+packed-FMA.
    if (l < 25) {
        int g  = w >> 1;
        int eh = w & 1;
        const float* row = &ss[g * 1875 + l * 75];
        const ulonglong2* vp = eh ? (const ulonglong2*)ve
                                  : (const ulonglong2*)&va[g * 600];
        unsigned long long acc[4];
        #pragma unroll
        for (int e = 0; e < 4; e++) acc[e] = 0ull;
        float sum = 0.f;
        for (int t = 0; t < 75; t++) {
            float e0 = row[t];
            sum += e0;
            unsigned long long pe = pack2(e0, e0);
            ulonglong2 vA = vp[t * 2];
            ulonglong2 vB = vp[t * 2 + 1];
            fma2(acc[0], pe, vA.x); fma2(acc[1], pe, vA.y);
            fma2(acc[2], pe, vB.x); fma2(acc[3], pe, vB.y);
        }
        float scale = (eh ? 0.1f : 1.0f) / sum;   // F_GV2=1.0, F_GV1=0.1
        float* op = &g_ret[b * 38400 + g * 4800 + u * 1200 + k * 400 + l * 16 + eh * 8];
        #pragma unroll
        for (int e = 0; e < 4; e++) {
            float lo, hi;
            unpack2(acc[e], lo, hi);
            op[e * 2]     = lo * scale;
            op[e * 2 + 1] = hi * scale;
        }
        if (eh == 0)
            g_bs[b * 2400 + g * 300 + u * 75 + k * 25 + l] = MFIX + __logf(sum);
    }
}

// ---------------- K4a: partial 32-channel sum-of-squares (coalesced) ----------------
__global__ __launch_bounds__(320)
void k4a_partial() {
    int b = blockIdx.x, q = blockIdx.y;
    int t = threadIdx.x;
    if (t >= 300) return;
    const float* p = &g_ret[b * 38400 + q * 32 * 300];
    float s = 0.f;
    #pragma unroll
    for (int c = 0; c < 32; c++) { float v = p[c * 300 + t]; s += v * v; }
    g_pn[(b * 4 + q) * 300 + t] = s;
}

// ---------------- K5: norms + bs-norm + unsort + hash softmax + output ----------------
__global__ __launch_bounds__(512)
void k5_out(float* __restrict__ out) {
    __shared__ float inrm[300];   // INVERSE channel norms
    __shared__ float bsn[300];
    __shared__ int   undo_s[NP];
    __shared__ float prob[NP];
    __shared__ int   off_s[NP];
    __shared__ int   mb_s[NP];
    int b = blockIdx.x;
    int n = b / 56, w = b % 56;
    int tid = threadIdx.x;

    for (int m = tid; m < 300; m += 512) {
        const float* pp = &g_pn[b * 1200 + m];
        float s = pp[0] + pp[300] + pp[600] + pp[900];
        inrm[m] = rsqrtf(fmaxf(s, EPS2));
    }
    for (int m = tid; m < 300; m += 512) {
        const float* p = &g_bs[b * 2400 + m];
        float vals[8], s = 0.f;
        #pragma unroll
        for (int g = 0; g < 8; g++) { vals[g] = p[g * 300]; s += vals[g] * vals[g]; }
        float inv = rsqrtf(fmaxf(s, EPS2));
        float t = 0.f;
        #pragma unroll
        for (int g = 0; g < 8; g++) t += vals[g] * inv;
        bsn[m] = t;
    }
    for (int j = tid; j < NP; j += 512) undo_s[j] = g_undo[b * NP + j];
    __syncthreads();

    if (tid < 56) {
        int h = tid;
        float bv[4];
        float mx = -1e30f;
        #pragma unroll
        for (int u = 0; u < 4; u++) {
            int q = undo_s[u * 56 + h];
            int qu = q / 56, qj = q % 56;
            int kk = qj / 25, i = qj % 25;
            bv[u] = bsn[qu * 75 + qj];
            off_s[u * 56 + h] = qu * 9600 + kk * 3200 + i * 128;
            int mb = kk * 200 + i * 128; mb %= 300;
            mb_s[u * 56 + h] = mb;
            mx = fmaxf(mx, bv[u]);
        }
        float sm = 0.f;
        #pragma unroll
        for (int u = 0; u < 4; u++) { bv[u] = __expf(bv[u] - mx); sm += bv[u]; }
        #pragma unroll
        for (int u = 0; u < 4; u++) prob[u * 56 + h] = bv[u] / sm;
    }
    __syncthreads();

    const float* rp = &g_ret[b * 38400];
    for (int idx = tid; idx < 56 * 64; idx += 512) {
        int h = idx / 64, o = idx % 64;
        float acc = 0.f;
        #pragma unroll
        for (int u = 0; u < 4; u++) {
            int e = u * 56 + h;
            int L0 = off_s[e] + o * 2;
            int m0 = mb_s[e] + o * 2; if (m0 >= 300) m0 -= 300;
            int m1 = m0 + 1;          if (m1 >= 300) m1 = 0;
            float x0 = rp[L0];
            float x1 = rp[L0 + 1];
            acc += prob[e] * (x0 * inrm[m0] + x1 * inrm[m1]);
        }
        out[((n * 64 + o) * 56 + h) * 56 + w] = acc;
    }
}

// ---------------- launch ----------------
extern "C" void kernel_launch(void* const* d_in, const int* in_sizes, int n_in,
                              void* d_out, int out_size) {
    const float* x        = (const float*)d_in[0];
    const float* cw       = (const float*)d_in[1];
    const float* gamma    = (const float*)d_in[2];
    const float* beta     = (const float*)d_in[3];
    const float* relative = (const float*)d_in[4];
    const float* rotations= (const float*)d_in[5];
    float* out = (float*)d_out;

    cudaFuncSetAttribute(k3_attn, cudaFuncAttributeMaxDynamicSharedMemorySize, 104704);

    dim3 g1(112, 2);
    k1_qkv <<<g1, 256>>>(x, cw, gamma, beta);
    k2_sort<<<112, 256>>>(rotations);
    dim3 g2b(112, 4);
    k2b_gather<<<g2b, 256>>>();
    k3_attn<<<Bb * 12, K3T, 104704>>>(relative);
    dim3 g4(112, 4);
    k4a_partial<<<g4, 320>>>();
    k5_out <<<112, 512>>>(out);
}